// round 3
// baseline (speedup 1.0000x reference)
#include <cuda_runtime.h>
#include <cuda_bf16.h>
#include <cstdint>
#include <math.h>

typedef __nv_bfloat16 bf16;

#define TOKENS 8192
#define Dm 1024
#define CTd 768
#define CBd 64
#define NE 8
#define Hh 1024
#define IDim 3072
#define GHd 1536
#define GH2d 768
#define H2d 512
#define H4d 256

// ------------------------- scratch (device globals, all fp32) ---------------
__device__ __align__(16) float g_ctn[(size_t)TOKENS*CTd];
__device__ __align__(16) float g_cbn[(size_t)TOKENS*CBd];
__device__ __align__(16) float g_x[(size_t)TOKENS*IDim];
__device__ __align__(16) float g_g1[(size_t)TOKENS*GHd];
__device__ __align__(16) float g_g1b[(size_t)TOKENS*GHd];
__device__ __align__(16) float g_g2[(size_t)TOKENS*GH2d];
__device__ __align__(16) float g_h1[(size_t)NE*TOKENS*Hh];
__device__ __align__(16) float g_h2[(size_t)NE*TOKENS*H2d];
__device__ __align__(16) float g_eo[(size_t)NE*TOKENS*H4d];
__device__ __align__(16) float g_comb[(size_t)TOKENS*H4d];
__device__ int   g_topi[TOKENS*2];
__device__ float g_topw[TOKENS*2];
__device__ int   g_pos[TOKENS*2];
__device__ int   g_tok[NE*TOKENS];
__device__ int   g_cnt[NE];
__device__ float g_Psum[NE];

// ------------------------- split-bf16 GEMM ----------------------------------
#define BM 128
#define BN 128
#define BK 32

enum { EP_PLAIN=0, EP_RELU=1, EP_RESID=2 };

// dynamic smem layout (bytes)
#define OFF_A32 0              // float [2][128][32]  = 32768
#define OFF_B32 32768          // float [2][32][128]  = 32768
#define OFF_AH  65536          // bf16 [128][40] = 10240
#define OFF_AL  75776
#define OFF_BH  86016          // bf16 [32][136] = 8704
#define OFF_BL  94720
#define SMEMB   103424

__device__ __forceinline__ void cpasync16(void* dst, const void* src){
    uint32_t d = (uint32_t)__cvta_generic_to_shared(dst);
    asm volatile("cp.async.cg.shared.global [%0], [%1], 16;\n" :: "r"(d), "l"(src));
}
__device__ __forceinline__ void split2(float x, bf16& h, bf16& l){
    h = __float2bfloat16(x);
    l = __float2bfloat16(x - __bfloat162float(h));
}

template<bool SPLIT>
__global__ __launch_bounds__(256)
void gemm_split(const float* __restrict__ A, int lda, long strideA,
                const float* __restrict__ Bw, int ldb, long strideB,
                const float* __restrict__ bias, int strideBias,
                float* __restrict__ C, int ldc, long strideC,
                int M, int N, int K, int mode,
                const int* __restrict__ gather, int strideG,
                const int* __restrict__ cntp,
                const float* __restrict__ resid, const float* __restrict__ alphap)
{
    extern __shared__ char smem[];
    float* As32 = (float*)(smem + OFF_A32);
    float* Bs32 = (float*)(smem + OFF_B32);
    bf16*  Ah   = (bf16*)(smem + OFF_AH);
    bf16*  Al   = (bf16*)(smem + OFF_AL);
    bf16*  Bh   = (bf16*)(smem + OFF_BH);
    bf16*  Bl   = (bf16*)(smem + OFF_BL);

    int e = blockIdx.z;
    int Meff = cntp ? cntp[e] : M;
    if ((int)blockIdx.y * BM >= Meff) return;
    A    += (long)e * strideA;
    Bw   += (long)e * strideB;
    bias += (long)e * strideBias;
    const int* gat = gather ? (gather + (long)e * strideG) : nullptr;

    int tid = threadIdx.x;
    int bm0 = blockIdx.y * BM;
    int bn0 = blockIdx.x * BN;

    float acc[4][4][4];
    #pragma unroll
    for (int i=0;i<4;i++)
        #pragma unroll
        for (int j=0;j<4;j++)
            #pragma unroll
            for (int k=0;k<4;k++) acc[i][j][k]=0.f;

    int warp = tid >> 5, lane = tid & 31;
    int wm = (warp & 1) * 64;
    int wn = (warp >> 1) * 32;
    int nk = K / BK;

    auto load_stage = [&](int s, int kt){
        int k0 = kt * BK;
        #pragma unroll
        for (int it=0; it<4; it++){
            int idx = tid + it*256;            // 1024 float4s for A
            int r = idx >> 3, c4 = (idx & 7) * 4;
            int grow = bm0 + r; if (grow >= Meff) grow = Meff - 1;
            if (gat) grow = gat[grow];
            cpasync16(&As32[s*4096 + r*32 + c4], A + (long)grow*lda + k0 + c4);
        }
        #pragma unroll
        for (int it=0; it<4; it++){
            int idx = tid + it*256;            // 1024 float4s for B
            int r = idx >> 5, c4 = (idx & 31) * 4;
            cpasync16(&Bs32[s*4096 + r*128 + c4], Bw + (long)(k0+r)*ldb + bn0 + c4);
        }
    };

    load_stage(0, 0);
    asm volatile("cp.async.commit_group;\n");

    for (int kt=0; kt<nk; kt++){
        int s = kt & 1;
        asm volatile("cp.async.wait_group 0;\n");
        __syncthreads();                        // staging ready; prior mma done
        if (kt+1 < nk){ load_stage(s^1, kt+1); asm volatile("cp.async.commit_group;\n"); }

        // convert f32 staging -> (hi[, lo]) bf16 tiles
        #pragma unroll
        for (int it=0; it<4; it++){
            int idx = tid + it*256;
            int r = idx >> 3, c = (idx & 7) * 4;
            float4 v = *(float4*)&As32[s*4096 + r*32 + c];
            bf16 h0,h1,h2,h3,l0,l1,l2,l3;
            split2(v.x,h0,l0); split2(v.y,h1,l1); split2(v.z,h2,l2); split2(v.w,h3,l3);
            *(__nv_bfloat162*)&Ah[r*40 + c]     = __nv_bfloat162(h0,h1);
            *(__nv_bfloat162*)&Ah[r*40 + c + 2] = __nv_bfloat162(h2,h3);
            if (SPLIT){
                *(__nv_bfloat162*)&Al[r*40 + c]     = __nv_bfloat162(l0,l1);
                *(__nv_bfloat162*)&Al[r*40 + c + 2] = __nv_bfloat162(l2,l3);
            }
        }
        #pragma unroll
        for (int it=0; it<4; it++){
            int idx = tid + it*256;
            int r = idx >> 5, c = (idx & 31) * 4;
            float4 v = *(float4*)&Bs32[s*4096 + r*128 + c];
            bf16 h0,h1,h2,h3,l0,l1,l2,l3;
            split2(v.x,h0,l0); split2(v.y,h1,l1); split2(v.z,h2,l2); split2(v.w,h3,l3);
            *(__nv_bfloat162*)&Bh[r*136 + c]     = __nv_bfloat162(h0,h1);
            *(__nv_bfloat162*)&Bh[r*136 + c + 2] = __nv_bfloat162(h2,h3);
            if (SPLIT){
                *(__nv_bfloat162*)&Bl[r*136 + c]     = __nv_bfloat162(l0,l1);
                *(__nv_bfloat162*)&Bl[r*136 + c + 2] = __nv_bfloat162(l2,l3);
            }
        }
        __syncthreads();                        // bf16 tiles ready

        #pragma unroll
        for (int ks=0; ks<2; ks++){
            uint32_t ah[4][4], al[4][4], bh[4][2], bl[4][2];
            #pragma unroll
            for (int mf=0; mf<4; mf++){
                int row = wm + mf*16 + (lane & 15);
                int col = ks*16 + ((lane >> 4) << 3);
                uint32_t addr = (uint32_t)__cvta_generic_to_shared(&Ah[row*40 + col]);
                asm volatile("ldmatrix.sync.aligned.m8n8.x4.shared.b16 {%0,%1,%2,%3}, [%4];\n"
                    : "=r"(ah[mf][0]),"=r"(ah[mf][1]),"=r"(ah[mf][2]),"=r"(ah[mf][3]) : "r"(addr));
                if (SPLIT){
                    addr = (uint32_t)__cvta_generic_to_shared(&Al[row*40 + col]);
                    asm volatile("ldmatrix.sync.aligned.m8n8.x4.shared.b16 {%0,%1,%2,%3}, [%4];\n"
                        : "=r"(al[mf][0]),"=r"(al[mf][1]),"=r"(al[mf][2]),"=r"(al[mf][3]) : "r"(addr));
                }
            }
            #pragma unroll
            for (int p=0; p<2; p++){
                int row = ks*16 + (lane & 15);
                int col = wn + p*16 + ((lane >> 4) << 3);
                uint32_t addr = (uint32_t)__cvta_generic_to_shared(&Bh[row*136 + col]);
                uint32_t r0,r1,r2,r3;
                asm volatile("ldmatrix.sync.aligned.m8n8.x4.trans.shared.b16 {%0,%1,%2,%3}, [%4];\n"
                    : "=r"(r0),"=r"(r1),"=r"(r2),"=r"(r3) : "r"(addr));
                bh[p*2][0]=r0; bh[p*2][1]=r1; bh[p*2+1][0]=r2; bh[p*2+1][1]=r3;
                if (SPLIT){
                    addr = (uint32_t)__cvta_generic_to_shared(&Bl[row*136 + col]);
                    asm volatile("ldmatrix.sync.aligned.m8n8.x4.trans.shared.b16 {%0,%1,%2,%3}, [%4];\n"
                        : "=r"(r0),"=r"(r1),"=r"(r2),"=r"(r3) : "r"(addr));
                    bl[p*2][0]=r0; bl[p*2][1]=r1; bl[p*2+1][0]=r2; bl[p*2+1][1]=r3;
                }
            }
            #pragma unroll
            for (int mf=0; mf<4; mf++)
                #pragma unroll
                for (int nf=0; nf<4; nf++){
                    asm volatile("mma.sync.aligned.m16n8k16.row.col.f32.bf16.bf16.f32 "
                        "{%0,%1,%2,%3},{%4,%5,%6,%7},{%8,%9},{%0,%1,%2,%3};\n"
                        : "+f"(acc[mf][nf][0]),"+f"(acc[mf][nf][1]),
                          "+f"(acc[mf][nf][2]),"+f"(acc[mf][nf][3])
                        : "r"(ah[mf][0]),"r"(ah[mf][1]),"r"(ah[mf][2]),"r"(ah[mf][3]),
                          "r"(bh[nf][0]),"r"(bh[nf][1]));
                    if (SPLIT){
                        asm volatile("mma.sync.aligned.m16n8k16.row.col.f32.bf16.bf16.f32 "
                            "{%0,%1,%2,%3},{%4,%5,%6,%7},{%8,%9},{%0,%1,%2,%3};\n"
                            : "+f"(acc[mf][nf][0]),"+f"(acc[mf][nf][1]),
                              "+f"(acc[mf][nf][2]),"+f"(acc[mf][nf][3])
                            : "r"(ah[mf][0]),"r"(ah[mf][1]),"r"(ah[mf][2]),"r"(ah[mf][3]),
                              "r"(bl[nf][0]),"r"(bl[nf][1]));
                        asm volatile("mma.sync.aligned.m16n8k16.row.col.f32.bf16.bf16.f32 "
                            "{%0,%1,%2,%3},{%4,%5,%6,%7},{%8,%9},{%0,%1,%2,%3};\n"
                            : "+f"(acc[mf][nf][0]),"+f"(acc[mf][nf][1]),
                              "+f"(acc[mf][nf][2]),"+f"(acc[mf][nf][3])
                            : "r"(al[mf][0]),"r"(al[mf][1]),"r"(al[mf][2]),"r"(al[mf][3]),
                              "r"(bh[nf][0]),"r"(bh[nf][1]));
                    }
                }
        }
        __syncthreads();                        // mma done before next convert
    }

    // epilogue
    float alpha = (mode==EP_RESID) ? alphap[0] : 0.f;
    #pragma unroll
    for (int mf=0; mf<4; mf++){
        #pragma unroll
        for (int nf=0; nf<4; nf++){
            int r0 = bm0 + wm + mf*16 + (lane >> 2);
            int c0 = bn0 + wn + nf*8 + (lane & 3)*2;
            #pragma unroll
            for (int half=0; half<2; half++){
                int r = r0 + half*8;
                if (r >= Meff) continue;
                float v0 = acc[mf][nf][half*2+0] + bias[c0];
                float v1 = acc[mf][nf][half*2+1] + bias[c0+1];
                long co = (long)e*strideC + (long)r*ldc + c0;
                if (mode == EP_RELU){ v0 = fmaxf(v0,0.f); v1 = fmaxf(v1,0.f); }
                if (mode == EP_RESID){
                    C[co]   = resid[co]   + alpha * v0;
                    C[co+1] = resid[co+1] + alpha * v1;
                } else {
                    C[co] = v0; C[co+1] = v1;
                }
            }
        }
    }
}

// ------------------------- reductions / LN ----------------------------------
__device__ __forceinline__ float2 block_sums256(float s, float q, float* sm){
    int lane = threadIdx.x & 31, w = threadIdx.x >> 5;
    #pragma unroll
    for (int o=16;o;o>>=1){ s += __shfl_xor_sync(0xffffffffu, s, o); q += __shfl_xor_sync(0xffffffffu, q, o); }
    if (lane==0){ sm[w]=s; sm[8+w]=q; }
    __syncthreads();
    if (threadIdx.x==0){
        float ts=0.f, tq=0.f;
        #pragma unroll
        for (int i=0;i<8;i++){ ts+=sm[i]; tq+=sm[8+i]; }
        sm[16]=ts; sm[17]=tq;
    }
    __syncthreads();
    float2 r = make_float2(sm[16], sm[17]);
    __syncthreads();
    return r;
}

__global__ void ln_f32_kernel(const float* __restrict__ src, float* __restrict__ dst,
                              int dim, const float* __restrict__ gam,
                              const float* __restrict__ bet, int relu){
    __shared__ float sm[18];
    long row = blockIdx.x;
    const float* x = src + row*dim;
    float s=0.f, q=0.f;
    for (int i=threadIdx.x; i<dim; i+=256){ float v=x[i]; s+=v; q+=v*v; }
    float2 t = block_sums256(s,q,sm);
    float m = t.x/dim;
    float inv = rsqrtf(t.y/dim - m*m + 1e-5f);
    for (int i=threadIdx.x; i<dim; i+=256){
        float v = (x[i]-m)*inv*gam[i] + bet[i];
        if (relu) v = fmaxf(v, 0.f);
        dst[row*dim + i] = v;
    }
}

__global__ void ln_h1_kernel(const float* __restrict__ gam, const float* __restrict__ bet){
    int e = blockIdx.y;
    int row = blockIdx.x;
    if (row >= g_cnt[e]) return;
    __shared__ float sm[18];
    float* x = g_h1 + ((size_t)e*TOKENS + row)*Hh;
    float s=0.f, q=0.f;
    for (int i=threadIdx.x; i<Hh; i+=256){ float v=x[i]; s+=v; q+=v*v; }
    float2 t = block_sums256(s,q,sm);
    float m = t.x/Hh;
    float inv = rsqrtf(t.y/Hh - m*m + 1e-5f);
    const float* ge = gam + e*Hh; const float* be = bet + e*Hh;
    for (int i=threadIdx.x; i<Hh; i+=256){
        float v = (x[i]-m)*inv*ge[i] + be[i];
        x[i] = fmaxf(v, 0.f);
    }
}

// ------------------------- misc small kernels -------------------------------
__global__ void zero_small(){
    int t = threadIdx.x;
    if (t < NE){ g_cnt[t]=0; g_Psum[t]=0.f; }
}

__global__ void build_x_id(const float* __restrict__ id){
    long i = (long)blockIdx.x*256 + threadIdx.x;
    if (i >= (long)TOKENS*Dm) return;
    long row = i >> 10; int col = (int)(i & 1023);
    g_x[row*IDim + col] = id[i];
}

__global__ void router_kernel(const float* __restrict__ Wg3, const float* __restrict__ bg3){
    __shared__ float smr[8*256];
    __shared__ float pr[8];
    int row = blockIdx.x, tid = threadIdx.x;
    float p[8];
    #pragma unroll
    for (int e=0;e<8;e++) p[e]=0.f;
    const float* xr = g_g2 + (long)row*GH2d;
    for (int k=tid; k<GH2d; k+=256){
        float a = xr[k];
        const float* wr = Wg3 + k*8;
        #pragma unroll
        for (int e=0;e<8;e++) p[e] += a*wr[e];
    }
    #pragma unroll
    for (int e=0;e<8;e++) smr[e*256+tid]=p[e];
    __syncthreads();
    if (tid < 8){
        float s=0.f;
        for (int j=0;j<256;j++) s += smr[tid*256+j];
        pr[tid] = s + bg3[tid];
    }
    __syncthreads();
    if (tid == 0){
        float mx = pr[0];
        #pragma unroll
        for (int e=1;e<8;e++) mx = fmaxf(mx, pr[e]);
        float ex[8]; float se=0.f;
        #pragma unroll
        for (int e=0;e<8;e++){ ex[e]=expf(pr[e]-mx); se+=ex[e]; }
        #pragma unroll
        for (int e=0;e<8;e++) ex[e] /= se;
        int i1=0;
        #pragma unroll
        for (int e=1;e<8;e++) if (ex[e] > ex[i1]) i1=e;
        int i2 = (i1==0)?1:0;
        #pragma unroll
        for (int e=0;e<8;e++) if (e!=i1 && ex[e] > ex[i2]) i2=e;
        float ssum = ex[i1]+ex[i2]+1e-8f;
        g_topi[row*2]=i1; g_topi[row*2+1]=i2;
        g_topw[row*2]=ex[i1]/ssum; g_topw[row*2+1]=ex[i2]/ssum;
        int p1 = atomicAdd(&g_cnt[i1],1); g_tok[i1*TOKENS+p1]=row; g_pos[row*2]=p1;
        int p2 = atomicAdd(&g_cnt[i2],1); g_tok[i2*TOKENS+p2]=row; g_pos[row*2+1]=p2;
        #pragma unroll
        for (int e=0;e<8;e++) pr[e]=ex[e];
    }
    __syncthreads();
    if (tid < 8) atomicAdd(&g_Psum[tid], pr[tid]);
}

__global__ void combine_kernel(const float* __restrict__ gam, const float* __restrict__ bet){
    __shared__ float sm[18];
    int row = blockIdx.x, tid = threadIdx.x;
    float out = 0.f;
    #pragma unroll
    for (int k=0;k<2;k++){
        int e = g_topi[row*2+k];
        int pos = g_pos[row*2+k];
        float w = g_topw[row*2+k];
        const float* x = g_eo + ((size_t)e*TOKENS + pos)*H4d;
        float v = x[tid];
        float2 t = block_sums256(v, v*v, sm);
        float m = t.x/H4d;
        float inv = rsqrtf(t.y/H4d - m*m + 1e-5f);
        float nv = (v-m)*inv*gam[e*H4d+tid] + bet[e*H4d+tid];
        out += w*nv;
    }
    g_comb[(long)row*H4d + tid] = out;
}

__global__ void lb_kernel(float* __restrict__ out){
    if (threadIdx.x == 0){
        float imp=0.f, ent=0.f;
        for (int e=0;e<8;e++){
            float f = (float)g_cnt[e] / (float)TOKENS;
            float P = g_Psum[e] / (float)TOKENS;
            imp += f*P;
            ent += -P*logf(P + 1e-8f);
        }
        imp *= 8.f;
        float me = logf(8.f);
        out[(long)TOKENS*Dm] = (imp + (me - ent)/me) * 0.01f;
    }
}

// ------------------------- host orchestration -------------------------------
static void launch_gemm(int split,
                        const float* A,int lda,long sA,const float* B,int ldb,long sB,
                        const float* bias,int sBias,float* C,int ldc,long sC,
                        int M,int N,int K,int mode,
                        const int* gather,int sG,const int* cnt,
                        const float* resid,const float* alphap,int nz)
{
    dim3 g(N/BN, (M+BM-1)/BM, nz);
    if (split)
        gemm_split<true><<<g,256,SMEMB>>>(A,lda,sA,B,ldb,sB,bias,sBias,C,ldc,sC,M,N,K,mode,gather,sG,cnt,resid,alphap);
    else
        gemm_split<false><<<g,256,SMEMB>>>(A,lda,sA,B,ldb,sB,bias,sBias,C,ldc,sC,M,N,K,mode,gather,sG,cnt,resid,alphap);
}

extern "C" void kernel_launch(void* const* d_in, const int* in_sizes, int n_in,
                              void* d_out, int out_size)
{
    const float* id_emb  = (const float*)d_in[0];
    const float* content = (const float*)d_in[1];
    const float* collab  = (const float*)d_in[2];
    const float* ln_ct_g = (const float*)d_in[3];
    const float* ln_ct_b = (const float*)d_in[4];
    const float* ln_cb_g = (const float*)d_in[5];
    const float* ln_cb_b = (const float*)d_in[6];
    const float* Wc   = (const float*)d_in[7];
    const float* bc   = (const float*)d_in[8];
    const float* Wcb  = (const float*)d_in[9];
    const float* bcb  = (const float*)d_in[10];
    const float* Wg1  = (const float*)d_in[11];
    const float* bg1  = (const float*)d_in[12];
    const float* lng_g= (const float*)d_in[13];
    const float* lng_b= (const float*)d_in[14];
    const float* Wg2  = (const float*)d_in[15];
    const float* bg2  = (const float*)d_in[16];
    const float* Wg3  = (const float*)d_in[17];
    const float* bg3  = (const float*)d_in[18];
    const float* We1  = (const float*)d_in[19];
    const float* be1  = (const float*)d_in[20];
    const float* lne1_g=(const float*)d_in[21];
    const float* lne1_b=(const float*)d_in[22];
    const float* We2  = (const float*)d_in[23];
    const float* be2  = (const float*)d_in[24];
    const float* We3  = (const float*)d_in[25];
    const float* be3  = (const float*)d_in[26];
    const float* lne3_g=(const float*)d_in[27];
    const float* lne3_b=(const float*)d_in[28];
    const float* Wout = (const float*)d_in[29];
    const float* bout = (const float*)d_in[30];
    const float* alpha= (const float*)d_in[31];
    float* out = (float*)d_out;

    cudaFuncSetAttribute(gemm_split<true>,  cudaFuncAttributeMaxDynamicSharedMemorySize, SMEMB);
    cudaFuncSetAttribute(gemm_split<false>, cudaFuncAttributeMaxDynamicSharedMemorySize, SMEMB);

    float *pctn,*pcbn,*px,*pg1,*pg1b,*pg2,*ph1,*ph2,*peo,*pcomb;
    int *ptok,*pcnt;
    cudaGetSymbolAddress((void**)&pctn, g_ctn);
    cudaGetSymbolAddress((void**)&pcbn, g_cbn);
    cudaGetSymbolAddress((void**)&px,   g_x);
    cudaGetSymbolAddress((void**)&pg1,  g_g1);
    cudaGetSymbolAddress((void**)&pg1b, g_g1b);
    cudaGetSymbolAddress((void**)&pg2,  g_g2);
    cudaGetSymbolAddress((void**)&ph1,  g_h1);
    cudaGetSymbolAddress((void**)&ph2,  g_h2);
    cudaGetSymbolAddress((void**)&peo,  g_eo);
    cudaGetSymbolAddress((void**)&pcomb,g_comb);
    cudaGetSymbolAddress((void**)&ptok, g_tok);
    cudaGetSymbolAddress((void**)&pcnt, g_cnt);

    // reset per-launch accumulators
    zero_small<<<1,32>>>();

    // x = concat(id, LN(ct)@Wc+bc, LN(cb)@Wcb+bcb)
    build_x_id<<<(TOKENS*Dm)/256,256>>>(id_emb);
    ln_f32_kernel<<<TOKENS,256>>>(content, pctn, CTd, ln_ct_g, ln_ct_b, 0);
    ln_f32_kernel<<<TOKENS,256>>>(collab,  pcbn, CBd, ln_cb_g, ln_cb_b, 0);
    launch_gemm(1, pctn, CTd, 0, Wc,  Dm, 0, bc,  0, px + Dm,   IDim, 0,
                TOKENS, Dm, CTd, EP_PLAIN, nullptr,0,nullptr,nullptr,nullptr,1);
    launch_gemm(1, pcbn, CBd, 0, Wcb, Dm, 0, bcb, 0, px + 2*Dm, IDim, 0,
                TOKENS, Dm, CBd, EP_PLAIN, nullptr,0,nullptr,nullptr,nullptr,1);

    // router (split precision: protects top-2 selection)
    launch_gemm(1, px, IDim, 0, Wg1, GHd, 0, bg1, 0, pg1, GHd, 0,
                TOKENS, GHd, IDim, EP_PLAIN, nullptr,0,nullptr,nullptr,nullptr,1);
    ln_f32_kernel<<<TOKENS,256>>>(pg1, pg1b, GHd, lng_g, lng_b, 1);
    launch_gemm(1, pg1b, GHd, 0, Wg2, GH2d, 0, bg2, 0, pg2, GH2d, 0,
                TOKENS, GH2d, GHd, EP_RELU, nullptr,0,nullptr,nullptr,nullptr,1);
    router_kernel<<<TOKENS,256>>>(Wg3, bg3);

    // experts (sparse, hi-only bf16: error scaled by alpha*ratio ~3%)
    launch_gemm(0, px, IDim, 0, We1, Hh, (long)IDim*Hh, be1, Hh,
                ph1, Hh, (long)TOKENS*Hh,
                TOKENS, Hh, IDim, EP_PLAIN, ptok, TOKENS, pcnt, nullptr,nullptr, NE);
    ln_h1_kernel<<<dim3(TOKENS,NE),256>>>(lne1_g, lne1_b);
    launch_gemm(0, ph1, Hh, (long)TOKENS*Hh, We2, H2d, (long)Hh*H2d, be2, H2d,
                ph2, H2d, (long)TOKENS*H2d,
                TOKENS, H2d, Hh, EP_RELU, nullptr,0, pcnt, nullptr,nullptr, NE);
    launch_gemm(0, ph2, H2d, (long)TOKENS*H2d, We3, H4d, (long)H2d*H4d, be3, H4d,
                peo, H4d, (long)TOKENS*H4d,
                TOKENS, H4d, H2d, EP_PLAIN, nullptr,0, pcnt, nullptr,nullptr, NE);
    combine_kernel<<<TOKENS,256>>>(lne3_g, lne3_b);

    // output projection + alpha residual
    launch_gemm(0, pcomb, H4d, 0, Wout, Dm, 0, bout, 0, out, Dm, 0,
                TOKENS, Dm, H4d, EP_RESID, nullptr,0,nullptr, id_emb, alpha, 1);

    // load-balancing loss scalar
    lb_kernel<<<1,32>>>(out);
}

// round 9
// speedup vs baseline: 1.0452x; 1.0452x over previous
#include <cuda_runtime.h>
#include <cuda_bf16.h>
#include <cstdint>
#include <math.h>

typedef __nv_bfloat16 bf16;

#define TOKENS 8192
#define Dm 1024
#define CTd 768
#define CBd 64
#define NE 8
#define Hh 1024
#define IDim 3072
#define GHd 1536
#define GH2d 768
#define H2d 512
#define H4d 256

// ------------------------- scratch (device globals) -------------------------
__device__ __align__(16) bf16 g_x3[(size_t)TOKENS*3*IDim];
__device__ __align__(16) bf16 g_xh[(size_t)TOKENS*IDim];
__device__ __align__(16) bf16 g_ctn3[(size_t)TOKENS*3*CTd];
__device__ __align__(16) bf16 g_cbn3[(size_t)TOKENS*3*CBd];
__device__ __align__(16) float g_g1[(size_t)TOKENS*GHd];
__device__ __align__(16) bf16 g_g1b3[(size_t)TOKENS*3*GHd];
__device__ __align__(16) float g_g2[(size_t)TOKENS*GH2d];
__device__ __align__(16) bf16 g_h1b[(size_t)NE*TOKENS*Hh];
__device__ __align__(16) bf16 g_h2[(size_t)NE*TOKENS*H2d];
__device__ __align__(16) float g_eo[(size_t)NE*TOKENS*H4d];
__device__ __align__(16) bf16 g_comb[(size_t)TOKENS*H4d];
// pre-transposed / pre-split weights (B side stored [N][K'] row-major)
__device__ __align__(16) bf16 g_Wc3t[(size_t)Dm*3*CTd];
__device__ __align__(16) bf16 g_Wcb3t[(size_t)Dm*3*CBd];
__device__ __align__(16) bf16 g_Wg13t[(size_t)GHd*3*IDim];
__device__ __align__(16) bf16 g_Wg23t[(size_t)GH2d*3*GHd];
__device__ __align__(16) bf16 g_We1t[(size_t)NE*Hh*IDim];
__device__ __align__(16) bf16 g_We2t[(size_t)NE*H2d*Hh];
__device__ __align__(16) bf16 g_We3t[(size_t)NE*H4d*H2d];
__device__ __align__(16) bf16 g_Woutt[(size_t)Dm*H4d];
__device__ int   g_topi[TOKENS*2];
__device__ float g_topw[TOKENS*2];
__device__ int   g_pos[TOKENS*2];
__device__ int   g_tok[NE*TOKENS];
__device__ int   g_cnt[NE];
__device__ float g_Psum[NE];

// ------------------------- helpers ------------------------------------------
__device__ __forceinline__ void cpa16(uint32_t d, const void* s){
    asm volatile("cp.async.cg.shared.global [%0], [%1], 16;\n" :: "r"(d), "l"(s));
}

// ------------------------- bf16 mma.sync GEMM --------------------------------
// C[M,N] = A[M,K] * Bt[N,K]^T ; tiles 128x128x64, 256 threads, double buffer.
enum { EP_F32=0, EP_F32_RELU=1, EP_BF16=2, EP_BF16_RELU=3, EP_X3=4, EP_RESID=5 };

#define LROW 72                     // padded row length (elems)
#define STAGE_B (2*128*LROW*2)      // bytes per stage (A+B tiles) = 36864
#define SMEM_MM (2*STAGE_B)         // 73728

__global__ __launch_bounds__(256)
void gemm_mma(const bf16* __restrict__ A, int lda, long strideA,
              const bf16* __restrict__ Bt, int ldbt, long strideB,
              const float* __restrict__ bias, int strideBias,
              void* __restrict__ Cp, int ldc, long strideC,
              bf16* __restrict__ C2, int ldc2, int col0,
              int M, int N, int K, int mode,
              const int* __restrict__ gather, int strideG,
              const int* __restrict__ cntp,
              const float* __restrict__ resid, const float* __restrict__ alphap)
{
    extern __shared__ __align__(16) char dsm[];
    int e = blockIdx.z;
    int Meff = cntp ? cntp[e] : M;
    int bm0 = blockIdx.y * 128;
    if (bm0 >= Meff) return;
    int bn0 = blockIdx.x * 128;
    A    += (long)e * strideA;
    Bt   += (long)e * strideB;
    bias += (long)e * strideBias;
    const int* gat = gather ? gather + (long)e * strideG : nullptr;

    int tid = threadIdx.x, warp = tid >> 5, lane = tid & 31;
    int wm = (warp & 1) * 64;
    int wn = (warp >> 1) * 32;

    uint32_t smb = (uint32_t)__cvta_generic_to_shared(dsm);

    // per-thread load sources (row fixed across K tiles)
    const bf16* aptr[4]; const bf16* bptr[4]; uint32_t adst[4], bdst[4];
    #pragma unroll
    for (int it=0; it<4; it++){
        int idx = tid + it*256;
        int r = idx >> 3, sub = idx & 7;
        uint32_t off = (uint32_t)(r*LROW*2 + sub*16);
        adst[it] = smb + off;
        bdst[it] = smb + 128*LROW*2 + off;
        int grow = bm0 + r; if (grow >= Meff) grow = Meff - 1;
        if (gat) grow = gat[grow];
        aptr[it] = A + (long)grow*lda + sub*8;
        bptr[it] = Bt + (long)(bn0 + r)*ldbt + sub*8;
    }

    float acc[4][4][4];
    #pragma unroll
    for (int i=0;i<4;i++)
        #pragma unroll
        for (int j=0;j<4;j++)
            #pragma unroll
            for (int k=0;k<4;k++) acc[i][j][k]=0.f;

    int nk = K >> 6;

    // prefetch stage 0
    #pragma unroll
    for (int it=0; it<4; it++){
        cpa16(adst[it], aptr[it]);
        cpa16(bdst[it], bptr[it]);
    }
    asm volatile("cp.async.commit_group;\n");

    uint32_t sa_base = smb;
    uint32_t sb_base = smb + 128*LROW*2;

    #pragma unroll 1
    for (int kt=0; kt<nk; kt++){
        int s = kt & 1;
        asm volatile("cp.async.wait_group 0;\n");
        __syncthreads();
        if (kt+1 < nk){
            int k0 = (kt+1) << 6;
            uint32_t so = (uint32_t)((s^1)*STAGE_B);
            #pragma unroll
            for (int it=0; it<4; it++){
                cpa16(adst[it] + so, aptr[it] + k0);
                cpa16(bdst[it] + so, bptr[it] + k0);
            }
            asm volatile("cp.async.commit_group;\n");
        }
        uint32_t sa = sa_base + s*STAGE_B;
        uint32_t sb = sb_base + s*STAGE_B;

        #pragma unroll
        for (int ks=0; ks<4; ks++){
            uint32_t a[4][4], b[4][2];
            #pragma unroll
            for (int mf=0; mf<4; mf++){
                int row = wm + mf*16 + (lane & 15);
                int col = ks*16 + ((lane >> 4) << 3);
                uint32_t addr = sa + (uint32_t)(row*LROW + col)*2;
                asm volatile("ldmatrix.sync.aligned.m8n8.x4.shared.b16 {%0,%1,%2,%3}, [%4];\n"
                    : "=r"(a[mf][0]),"=r"(a[mf][1]),"=r"(a[mf][2]),"=r"(a[mf][3]) : "r"(addr));
            }
            #pragma unroll
            for (int g=0; g<2; g++){
                int row = wn + g*16 + ((lane >> 4) << 3) + (lane & 7);
                int col = ks*16 + (((lane >> 3) & 1) << 3);
                uint32_t addr = sb + (uint32_t)(row*LROW + col)*2;
                uint32_t r0,r1,r2,r3;
                asm volatile("ldmatrix.sync.aligned.m8n8.x4.shared.b16 {%0,%1,%2,%3}, [%4];\n"
                    : "=r"(r0),"=r"(r1),"=r"(r2),"=r"(r3) : "r"(addr));
                b[g*2][0]=r0; b[g*2][1]=r1; b[g*2+1][0]=r2; b[g*2+1][1]=r3;
            }
            #pragma unroll
            for (int mf=0; mf<4; mf++)
                #pragma unroll
                for (int nf=0; nf<4; nf++){
                    asm volatile("mma.sync.aligned.m16n8k16.row.col.f32.bf16.bf16.f32 "
                        "{%0,%1,%2,%3},{%4,%5,%6,%7},{%8,%9},{%0,%1,%2,%3};\n"
                        : "+f"(acc[mf][nf][0]),"+f"(acc[mf][nf][1]),
                          "+f"(acc[mf][nf][2]),"+f"(acc[mf][nf][3])
                        : "r"(a[mf][0]),"r"(a[mf][1]),"r"(a[mf][2]),"r"(a[mf][3]),
                          "r"(b[nf][0]),"r"(b[nf][1]));
                }
        }
        __syncthreads();
    }

    // ------------- epilogue -------------
    float alphav = (mode == EP_RESID) ? alphap[0] : 0.f;
    #pragma unroll
    for (int mf=0; mf<4; mf++){
        #pragma unroll
        for (int nf=0; nf<4; nf++){
            int r0 = bm0 + wm + mf*16 + (lane >> 2);
            int c0 = bn0 + wn + nf*8 + (lane & 3)*2;
            #pragma unroll
            for (int half=0; half<2; half++){
                int r = r0 + half*8;
                if (r >= Meff) continue;
                float v0 = acc[mf][nf][half*2+0] + bias[c0];
                float v1 = acc[mf][nf][half*2+1] + bias[c0+1];
                if (mode == EP_X3){
                    bf16* C3 = (bf16*)Cp;
                    long ro3 = (long)r*ldc;
                    long ro2 = (long)r*ldc2;
                    bf16 h0 = __float2bfloat16(v0);
                    bf16 l0 = __float2bfloat16(v0 - __bfloat162float(h0));
                    bf16 h1 = __float2bfloat16(v1);
                    bf16 l1 = __float2bfloat16(v1 - __bfloat162float(h1));
                    long o0 = ro3 + 3L*(col0 + c0);
                    C3[o0]   = h0; C3[o0+1] = l0; C3[o0+2] = h0;
                    C3[o0+3] = h1; C3[o0+4] = l1; C3[o0+5] = h1;
                    C2[ro2 + col0 + c0]     = h0;
                    C2[ro2 + col0 + c0 + 1] = h1;
                } else if (mode == EP_RESID){
                    float* C = (float*)Cp;
                    long co = (long)e*strideC + (long)r*ldc + c0;
                    C[co]   = resid[co]   + alphav * v0;
                    C[co+1] = resid[co+1] + alphav * v1;
                } else if (mode == EP_F32 || mode == EP_F32_RELU){
                    if (mode == EP_F32_RELU){ v0 = fmaxf(v0,0.f); v1 = fmaxf(v1,0.f); }
                    float* C = (float*)Cp;
                    long co = (long)e*strideC + (long)r*ldc + c0;
                    C[co] = v0; C[co+1] = v1;
                } else {
                    if (mode == EP_BF16_RELU){ v0 = fmaxf(v0,0.f); v1 = fmaxf(v1,0.f); }
                    bf16* C = (bf16*)Cp;
                    long co = (long)e*strideC + (long)r*ldc + c0;
                    C[co] = __float2bfloat16(v0); C[co+1] = __float2bfloat16(v1);
                }
            }
        }
    }
}

// ------------------------- weight preprocessing -----------------------------
// hi-only transpose: src f32 [K][N] -> dst bf16 [N][K]
__global__ void wt_hi_kernel(const float* __restrict__ src, bf16* __restrict__ dst,
                             int K, int N){
    __shared__ float t[32][33];
    int e = blockIdx.z;
    src += (long)e*K*N; dst += (long)e*N*K;
    int k0 = blockIdx.x*32, n0 = blockIdx.y*32;
    int tx = threadIdx.x & 31, ty = threadIdx.x >> 5;
    #pragma unroll
    for (int i=0; i<32; i+=8)
        t[ty+i][tx] = src[(long)(k0+ty+i)*N + n0 + tx];
    __syncthreads();
    #pragma unroll
    for (int i=0; i<32; i+=8)
        dst[(long)(n0+ty+i)*K + k0 + tx] = __float2bfloat16(t[tx][ty+i]);
}

// triple transpose: src f32 [K][N] -> dst bf16 [N][3K], triples (h,h,l)
__global__ void wt_tri_kernel(const float* __restrict__ src, bf16* __restrict__ dst,
                              int K, int N){
    __shared__ float t[32][33];
    int k0 = blockIdx.x*32, n0 = blockIdx.y*32;
    int tx = threadIdx.x & 31, ty = threadIdx.x >> 5;
    #pragma unroll
    for (int i=0; i<32; i+=8)
        t[ty+i][tx] = src[(long)(k0+ty+i)*N + n0 + tx];
    __syncthreads();
    #pragma unroll
    for (int i=0; i<32; i+=8){
        float v = t[tx][ty+i];
        bf16 h = __float2bfloat16(v);
        bf16 l = __float2bfloat16(v - __bfloat162float(h));
        long o = (long)(n0+ty+i)*(3*K) + 3*(long)(k0+tx);
        dst[o] = h; dst[o+1] = h; dst[o+2] = l;
    }
}

// ------------------------- reductions / LN ----------------------------------
__device__ __forceinline__ float2 block_sums256(float s, float q, float* sm){
    int lane = threadIdx.x & 31, w = threadIdx.x >> 5;
    #pragma unroll
    for (int o=16;o;o>>=1){ s += __shfl_xor_sync(0xffffffffu, s, o); q += __shfl_xor_sync(0xffffffffu, q, o); }
    if (lane==0){ sm[w]=s; sm[8+w]=q; }
    __syncthreads();
    if (threadIdx.x==0){
        float ts=0.f, tq=0.f;
        #pragma unroll
        for (int i=0;i<8;i++){ ts+=sm[i]; tq+=sm[8+i]; }
        sm[16]=ts; sm[17]=tq;
    }
    __syncthreads();
    float2 r = make_float2(sm[16], sm[17]);
    __syncthreads();
    return r;
}

// LN f32 -> triple bf16 (h,l,h) layout, optional relu
__global__ void ln_triple_kernel(const float* __restrict__ src, bf16* __restrict__ dst,
                                 int dim, const float* __restrict__ gam,
                                 const float* __restrict__ bet, int relu){
    __shared__ float sm[18];
    long row = blockIdx.x;
    const float* x = src + row*dim;
    float s=0.f, q=0.f;
    for (int i=threadIdx.x; i<dim; i+=256){ float v=x[i]; s+=v; q+=v*v; }
    float2 t = block_sums256(s,q,sm);
    float m = t.x/dim;
    float inv = rsqrtf(t.y/dim - m*m + 1e-5f);
    bf16* d = dst + row*(3L*dim);
    for (int i=threadIdx.x; i<dim; i+=256){
        float v = (x[i]-m)*inv*gam[i] + bet[i];
        if (relu) v = fmaxf(v, 0.f);
        bf16 h = __float2bfloat16(v);
        bf16 l = __float2bfloat16(v - __bfloat162float(h));
        d[3*i] = h; d[3*i+1] = l; d[3*i+2] = h;
    }
}

// LN bf16 in/out (+relu) for expert h1 rows
__global__ void ln_h1b_kernel(const float* __restrict__ gam, const float* __restrict__ bet){
    int e = blockIdx.y;
    int row = blockIdx.x;
    if (row >= g_cnt[e]) return;
    __shared__ float sm[18];
    bf16* x = g_h1b + ((size_t)e*TOKENS + row)*Hh;
    float s=0.f, q=0.f;
    for (int i=threadIdx.x; i<Hh; i+=256){ float v=__bfloat162float(x[i]); s+=v; q+=v*v; }
    float2 t = block_sums256(s,q,sm);
    float m = t.x/Hh;
    float inv = rsqrtf(t.y/Hh - m*m + 1e-5f);
    const float* ge = gam + e*Hh; const float* be = bet + e*Hh;
    for (int i=threadIdx.x; i<Hh; i+=256){
        float v = (__bfloat162float(x[i])-m)*inv*ge[i] + be[i];
        x[i] = __float2bfloat16(fmaxf(v, 0.f));
    }
}

// ------------------------- misc small kernels -------------------------------
__global__ void zero_small(){
    int t = threadIdx.x;
    if (t < NE){ g_cnt[t]=0; g_Psum[t]=0.f; }
}

__global__ void build_x_id(const float* __restrict__ id){
    long i = (long)blockIdx.x*256 + threadIdx.x;
    if (i >= (long)TOKENS*Dm) return;
    long row = i >> 10; int col = (int)(i & 1023);
    float v = id[i];
    bf16 h = __float2bfloat16(v);
    bf16 l = __float2bfloat16(v - __bfloat162float(h));
    bf16* d = g_x3 + row*(3L*IDim) + 3L*col;
    d[0] = h; d[1] = l; d[2] = h;
    g_xh[row*IDim + col] = h;
}

__global__ void router_kernel(const float* __restrict__ Wg3, const float* __restrict__ bg3){
    __shared__ float smr[8*256];
    __shared__ float pr[8];
    int row = blockIdx.x, tid = threadIdx.x;
    float p[8];
    #pragma unroll
    for (int e=0;e<8;e++) p[e]=0.f;
    const float* xr = g_g2 + (long)row*GH2d;
    for (int k=tid; k<GH2d; k+=256){
        float a = xr[k];
        const float* wr = Wg3 + k*8;
        #pragma unroll
        for (int e=0;e<8;e++) p[e] += a*wr[e];
    }
    #pragma unroll
    for (int e=0;e<8;e++) smr[e*256+tid]=p[e];
    __syncthreads();
    if (tid < 8){
        float s=0.f;
        for (int j=0;j<256;j++) s += smr[tid*256+j];
        pr[tid] = s + bg3[tid];
    }
    __syncthreads();
    if (tid == 0){
        float mx = pr[0];
        #pragma unroll
        for (int e=1;e<8;e++) mx = fmaxf(mx, pr[e]);
        float ex[8]; float se=0.f;
        #pragma unroll
        for (int e=0;e<8;e++){ ex[e]=expf(pr[e]-mx); se+=ex[e]; }
        #pragma unroll
        for (int e=0;e<8;e++) ex[e] /= se;
        int i1=0;
        #pragma unroll
        for (int e=1;e<8;e++) if (ex[e] > ex[i1]) i1=e;
        int i2 = (i1==0)?1:0;
        #pragma unroll
        for (int e=0;e<8;e++) if (e!=i1 && ex[e] > ex[i2]) i2=e;
        float ssum = ex[i1]+ex[i2]+1e-8f;
        g_topi[row*2]=i1; g_topi[row*2+1]=i2;
        g_topw[row*2]=ex[i1]/ssum; g_topw[row*2+1]=ex[i2]/ssum;
        int p1 = atomicAdd(&g_cnt[i1],1); g_tok[i1*TOKENS+p1]=row; g_pos[row*2]=p1;
        int p2 = atomicAdd(&g_cnt[i2],1); g_tok[i2*TOKENS+p2]=row; g_pos[row*2+1]=p2;
        #pragma unroll
        for (int e=0;e<8;e++) pr[e]=ex[e];
    }
    __syncthreads();
    if (tid < 8) atomicAdd(&g_Psum[tid], pr[tid]);
}

__global__ void combine_kernel(const float* __restrict__ gam, const float* __restrict__ bet){
    __shared__ float sm[18];
    int row = blockIdx.x, tid = threadIdx.x;
    float out = 0.f;
    #pragma unroll
    for (int k=0;k<2;k++){
        int e = g_topi[row*2+k];
        int pos = g_pos[row*2+k];
        float w = g_topw[row*2+k];
        const float* x = g_eo + ((size_t)e*TOKENS + pos)*H4d;
        float v = x[tid];
        float2 t = block_sums256(v, v*v, sm);
        float m = t.x/H4d;
        float inv = rsqrtf(t.y/H4d - m*m + 1e-5f);
        float nv = (v-m)*inv*gam[e*H4d+tid] + bet[e*H4d+tid];
        out += w*nv;
    }
    g_comb[(long)row*H4d + tid] = __float2bfloat16(out);
}

__global__ void lb_kernel(float* __restrict__ out){
    if (threadIdx.x == 0){
        float imp=0.f, ent=0.f;
        for (int e=0;e<8;e++){
            float f = (float)g_cnt[e] / (float)TOKENS;
            float P = g_Psum[e] / (float)TOKENS;
            imp += f*P;
            ent += -P*logf(P + 1e-8f);
        }
        imp *= 8.f;
        float me = logf(8.f);
        out[(long)TOKENS*Dm] = (imp + (me - ent)/me) * 0.01f;
    }
}

// ------------------------- host orchestration -------------------------------
static void ggemm(const bf16* A,int lda,long sA,const bf16* Bt,int ldbt,long sB,
                  const float* bias,int sBias,void* C,int ldc,long sC,
                  bf16* C2,int ldc2,int col0,
                  int M,int N,int K,int mode,
                  const int* gat,int sG,const int* cnt,
                  const float* resid,const float* alphap,int nz)
{
    dim3 g(N/128, (M+127)/128, nz);
    gemm_mma<<<g,256,SMEM_MM>>>(A,lda,sA,Bt,ldbt,sB,bias,sBias,C,ldc,sC,C2,ldc2,col0,
                                M,N,K,mode,gat,sG,cnt,resid,alphap);
}

extern "C" void kernel_launch(void* const* d_in, const int* in_sizes, int n_in,
                              void* d_out, int out_size)
{
    const float* id_emb  = (const float*)d_in[0];
    const float* content = (const float*)d_in[1];
    const float* collab  = (const float*)d_in[2];
    const float* ln_ct_g = (const float*)d_in[3];
    const float* ln_ct_b = (const float*)d_in[4];
    const float* ln_cb_g = (const float*)d_in[5];
    const float* ln_cb_b = (const float*)d_in[6];
    const float* Wc   = (const float*)d_in[7];
    const float* bc   = (const float*)d_in[8];
    const float* Wcb  = (const float*)d_in[9];
    const float* bcb  = (const float*)d_in[10];
    const float* Wg1  = (const float*)d_in[11];
    const float* bg1  = (const float*)d_in[12];
    const float* lng_g= (const float*)d_in[13];
    const float* lng_b= (const float*)d_in[14];
    const float* Wg2  = (const float*)d_in[15];
    const float* bg2  = (const float*)d_in[16];
    const float* Wg3  = (const float*)d_in[17];
    const float* bg3  = (const float*)d_in[18];
    const float* We1  = (const float*)d_in[19];
    const float* be1  = (const float*)d_in[20];
    const float* lne1_g=(const float*)d_in[21];
    const float* lne1_b=(const float*)d_in[22];
    const float* We2  = (const float*)d_in[23];
    const float* be2  = (const float*)d_in[24];
    const float* We3  = (const float*)d_in[25];
    const float* be3  = (const float*)d_in[26];
    const float* lne3_g=(const float*)d_in[27];
    const float* lne3_b=(const float*)d_in[28];
    const float* Wout = (const float*)d_in[29];
    const float* bout = (const float*)d_in[30];
    const float* alpha= (const float*)d_in[31];
    float* out = (float*)d_out;

    cudaFuncSetAttribute(gemm_mma, cudaFuncAttributeMaxDynamicSharedMemorySize, SMEM_MM);

    bf16 *px3,*pxh,*pctn3,*pcbn3,*pg1b3,*ph1b,*ph2,*pcomb;
    bf16 *pWc3t,*pWcb3t,*pWg13t,*pWg23t,*pWe1t,*pWe2t,*pWe3t,*pWoutt;
    float *pg1,*pg2,*peo;
    int *ptok,*pcnt;
    cudaGetSymbolAddress((void**)&px3,   g_x3);
    cudaGetSymbolAddress((void**)&pxh,   g_xh);
    cudaGetSymbolAddress((void**)&pctn3, g_ctn3);
    cudaGetSymbolAddress((void**)&pcbn3, g_cbn3);
    cudaGetSymbolAddress((void**)&pg1,   g_g1);
    cudaGetSymbolAddress((void**)&pg1b3, g_g1b3);
    cudaGetSymbolAddress((void**)&pg2,   g_g2);
    cudaGetSymbolAddress((void**)&ph1b,  g_h1b);
    cudaGetSymbolAddress((void**)&ph2,   g_h2);
    cudaGetSymbolAddress((void**)&peo,   g_eo);
    cudaGetSymbolAddress((void**)&pcomb, g_comb);
    cudaGetSymbolAddress((void**)&pWc3t, g_Wc3t);
    cudaGetSymbolAddress((void**)&pWcb3t,g_Wcb3t);
    cudaGetSymbolAddress((void**)&pWg13t,g_Wg13t);
    cudaGetSymbolAddress((void**)&pWg23t,g_Wg23t);
    cudaGetSymbolAddress((void**)&pWe1t, g_We1t);
    cudaGetSymbolAddress((void**)&pWe2t, g_We2t);
    cudaGetSymbolAddress((void**)&pWe3t, g_We3t);
    cudaGetSymbolAddress((void**)&pWoutt,g_Woutt);
    cudaGetSymbolAddress((void**)&ptok,  g_tok);
    cudaGetSymbolAddress((void**)&pcnt,  g_cnt);

    zero_small<<<1,32>>>();

    // weight preprocessing
    wt_tri_kernel<<<dim3(CTd/32, Dm/32, 1), 256>>>(Wc,  pWc3t,  CTd,  Dm);
    wt_tri_kernel<<<dim3(CBd/32, Dm/32, 1), 256>>>(Wcb, pWcb3t, CBd,  Dm);
    wt_tri_kernel<<<dim3(IDim/32, GHd/32, 1), 256>>>(Wg1, pWg13t, IDim, GHd);
    wt_tri_kernel<<<dim3(GHd/32, GH2d/32, 1), 256>>>(Wg2, pWg23t, GHd,  GH2d);
    wt_hi_kernel<<<dim3(IDim/32, Hh/32, NE), 256>>>(We1, pWe1t, IDim, Hh);
    wt_hi_kernel<<<dim3(Hh/32, H2d/32, NE), 256>>>(We2, pWe2t, Hh, H2d);
    wt_hi_kernel<<<dim3(H2d/32, H4d/32, NE), 256>>>(We3, pWe3t, H2d, H4d);
    wt_hi_kernel<<<dim3(H4d/32, Dm/32, 1), 256>>>(Wout, pWoutt, H4d, Dm);

    // x = concat(id, LN(ct)@Wc+bc, LN(cb)@Wcb+bcb) — triple + hi layouts
    build_x_id<<<(TOKENS*Dm)/256, 256>>>(id_emb);
    ln_triple_kernel<<<TOKENS,256>>>(content, pctn3, CTd, ln_ct_g, ln_ct_b, 0);
    ln_triple_kernel<<<TOKENS,256>>>(collab,  pcbn3, CBd, ln_cb_g, ln_cb_b, 0);
    ggemm(pctn3, 3*CTd, 0, pWc3t, 3*CTd, 0, bc, 0, px3, 3*IDim, 0,
          pxh, IDim, Dm, TOKENS, Dm, 3*CTd, EP_X3, nullptr,0,nullptr,nullptr,nullptr,1);
    ggemm(pcbn3, 3*CBd, 0, pWcb3t, 3*CBd, 0, bcb, 0, px3, 3*IDim, 0,
          pxh, IDim, 2*Dm, TOKENS, Dm, 3*CBd, EP_X3, nullptr,0,nullptr,nullptr,nullptr,1);

    // router (split precision via triple layouts)
    ggemm(px3, 3*IDim, 0, pWg13t, 3*IDim, 0, bg1, 0, pg1, GHd, 0,
          nullptr, 0, 0, TOKENS, GHd, 3*IDim, EP_F32, nullptr,0,nullptr,nullptr,nullptr,1);
    ln_triple_kernel<<<TOKENS,256>>>(pg1, pg1b3, GHd, lng_g, lng_b, 1);
    ggemm(pg1b3, 3*GHd, 0, pWg23t, 3*GHd, 0, bg2, 0, pg2, GH2d, 0,
          nullptr, 0, 0, TOKENS, GH2d, 3*GHd, EP_F32_RELU, nullptr,0,nullptr,nullptr,nullptr,1);
    router_kernel<<<TOKENS,256>>>(Wg3, bg3);

    // experts (sparse, hi-only bf16)
    ggemm(pxh, IDim, 0, pWe1t, IDim, (long)Hh*IDim, be1, Hh,
          ph1b, Hh, (long)TOKENS*Hh, nullptr, 0, 0,
          TOKENS, Hh, IDim, EP_BF16, ptok, TOKENS, pcnt, nullptr,nullptr, NE);
    ln_h1b_kernel<<<dim3(TOKENS,NE),256>>>(lne1_g, lne1_b);
    ggemm(ph1b, Hh, (long)TOKENS*Hh, pWe2t, Hh, (long)H2d*Hh, be2, H2d,
          ph2, H2d, (long)TOKENS*H2d, nullptr, 0, 0,
          TOKENS, H2d, Hh, EP_BF16_RELU, nullptr,0, pcnt, nullptr,nullptr, NE);
    ggemm(ph2, H2d, (long)TOKENS*H2d, pWe3t, H2d, (long)H4d*H2d, be3, H4d,
          peo, H4d, (long)TOKENS*H4d, nullptr, 0, 0,
          TOKENS, H4d, H2d, EP_F32, nullptr,0, pcnt, nullptr,nullptr, NE);
    combine_kernel<<<TOKENS,256>>>(lne3_g, lne3_b);

    // output projection + alpha residual
    ggemm(pcomb, H4d, 0, pWoutt, H4d, 0, bout, 0, out, Dm, 0,
          nullptr, 0, 0, TOKENS, Dm, H4d, EP_RESID, nullptr,0,nullptr, id_emb, alpha, 1);

    // load-balancing loss scalar
    lb_kernel<<<1,32>>>(out);
}